// round 1
// baseline (speedup 1.0000x reference)
#include <cuda_runtime.h>

// Interpolate1D: stride-2 linear upsample along dim 1.
// in:  [B=16, N=8192, C=256] fp32
// out: [B, 2N, C] fp32
//   out[b, 2k,   c] = x[b, k, c]
//   out[b, 2k+1, c] = 0.5*(x[b,k,c] + x[b,k+1,c])  (k < N-1)
//   out[b, 2N-1, c] = x[b, N-1, c]

namespace {
constexpr int B = 16;
constexpr int N = 8192;
constexpr int C = 256;
constexpr int C4 = C / 4;                 // 64 float4 per row
constexpr long TOTAL4 = (long)B * N * C4; // 8,388,608 threads
}

__global__ void interp1d_kernel(const float4* __restrict__ x,
                                float4* __restrict__ y) {
    long i = (long)blockIdx.x * blockDim.x + threadIdx.x;
    if (i >= TOTAL4) return;

    int c  = (int)(i & (C4 - 1));   // float4 column within row
    long bn = i >> 6;               // flattened (b*N + k)
    int k  = (int)(bn & (N - 1));

    float4 cur = x[i];
    float4 nxt = (k < N - 1) ? x[i + C4] : cur;

    float4 mid;
    mid.x = 0.5f * (cur.x + nxt.x);
    mid.y = 0.5f * (cur.y + nxt.y);
    mid.z = 0.5f * (cur.z + nxt.z);
    mid.w = 0.5f * (cur.w + nxt.w);

    // output row index = b*2N + 2k = 2*bn  (and 2*bn+1 for midpoint)
    long o = (bn << 1) * C4 + c;
    y[o]      = cur;
    y[o + C4] = mid;
}

extern "C" void kernel_launch(void* const* d_in, const int* in_sizes, int n_in,
                              void* d_out, int out_size) {
    const float4* x = (const float4*)d_in[0];
    float4* y = (float4*)d_out;

    const int threads = 256;
    const long blocks = (TOTAL4 + threads - 1) / threads;
    interp1d_kernel<<<(unsigned)blocks, threads>>>(x, y);
}